// round 1
// baseline (speedup 1.0000x reference)
#include <cuda_runtime.h>

// ---------------------------------------------------------------------------
// KF_20332375179766 : batched square-root Kalman filter
// B=2048 batches, T=1000 steps, n=d=8.
// Phase 1: single-block sequential Riccati (batch-independent), produces
//          A_t = (I-K_t H)F and K_t per step + Ps output. Freezes after
//          numerical convergence (recursion is contracting).
// Phase 2: per-batch linear recursion x_t = A_t x_{t-1} + K_t y_t,
//          8 lanes/batch, shuffle matvec, cp.async staged A/K chunks.
// ---------------------------------------------------------------------------

#define TCAP 1024
// per t: [0..71] A (8x8, row stride 9), [72..143] K (row stride 9)
__device__ __align__(16) float g_AK[TCAP * 144];

// ============================ Phase 1 ======================================

__global__ void __launch_bounds__(64) riccati_kernel(
    const float* __restrict__ Fg, const float* __restrict__ Gg,
    const float* __restrict__ Hg, const float* __restrict__ Qg,
    const float* __restrict__ Rg, const float* __restrict__ P0g,
    float* __restrict__ Ps_out, int T)
{
    __shared__ float sF[72], sH[72], sHF[72], sGQG[72], sR[72];
    __shared__ float sP[72], sT1[72], sPn[72], sK[72], sTmp[72], sQ[72];
    __shared__ float sST2[160];   // S at [0..71], T2 at [80..151]
    __shared__ float sRed[4];
    __shared__ int   sFlag;

    const int tid = threadIdx.x;
    const int i = tid >> 3, j = tid & 7;
    const int ij9 = i * 9 + j;

    // load inputs (8x8, row-major) into padded (stride-9) shared tiles
    sF[ij9] = Fg[tid];  sH[ij9] = Hg[tid];  sR[ij9] = Rg[tid];
    sP[ij9] = P0g[tid]; sQ[ij9] = Qg[tid];  sTmp[ij9] = Gg[tid];  // sTmp = G
    if (tid == 0) sFlag = 0;
    __syncthreads();

    // init: GQG^T = G*Q*G^T, HF = H*F
    {
        float m1 = 0.f, hf = 0.f;
        #pragma unroll
        for (int k = 0; k < 8; k++) {
            m1 += sTmp[i*9+k] * sQ[k*9+j];   // (G*Q)[i][j]
            hf += sH[i*9+k]   * sF[k*9+j];   // (H*F)[i][j]
        }
        sPn[ij9] = m1; sHF[ij9] = hf;
        __syncthreads();
        float gq = 0.f;
        #pragma unroll
        for (int k = 0; k < 8; k++) gq += sPn[i*9+k] * sTmp[j*9+k]; // (GQ)*G^T
        sGQG[ij9] = gq;
        __syncthreads();
    }

    int conv = 0;
    for (int t = 0; t < T; t++) {
        // T1 = F * P
        {
            float a = 0.f;
            #pragma unroll
            for (int k = 0; k < 8; k++) a += sF[i*9+k] * sP[k*9+j];
            sT1[ij9] = a;
        }
        __syncthreads();
        // Pn = T1 * F^T + GQG
        {
            float a = sGQG[ij9];
            #pragma unroll
            for (int k = 0; k < 8; k++) a += sT1[i*9+k] * sF[j*9+k];
            sPn[ij9] = a;
        }
        __syncthreads();
        // T2 = H * Pn
        {
            float a = 0.f;
            #pragma unroll
            for (int k = 0; k < 8; k++) a += sH[i*9+k] * sPn[k*9+j];
            sST2[80 + ij9] = a;
        }
        __syncthreads();
        // S = T2 * H^T + R
        {
            float a = sR[ij9];
            #pragma unroll
            for (int k = 0; k < 8; k++) a += sST2[80 + i*9+k] * sH[j*9+k];
            sST2[ij9] = a;
        }
        __syncthreads();

        // Gauss-Jordan on [S | T2]  (16 lanes, each owns one column).
        // Solves S * X = T2  ->  X = S^{-1} H Pn = K^T.  Lane 8+c ends up
        // holding column c of K^T, i.e. row c of K.
        if (tid < 16) {
            float a[8];
            const int base = (tid < 8) ? tid : (80 + tid - 8);
            #pragma unroll
            for (int r = 0; r < 8; r++) a[r] = sST2[base + r*9];
            #pragma unroll
            for (int p = 0; p < 8; p++) {
                float c[8];
                #pragma unroll
                for (int r = 0; r < 8; r++)
                    c[r] = __shfl_sync(0x0000FFFFu, a[r], p, 16);
                float pr = 1.0f / c[p];
                a[p] *= pr;
                #pragma unroll
                for (int r = 0; r < 8; r++)
                    if (r != p) a[r] = fmaf(-c[r], a[p], a[r]);
            }
            if (tid >= 8) {
                const int row = tid - 8;     // K row index
                #pragma unroll
                for (int r = 0; r < 8; r++) sK[row*9 + r] = a[r];
            }
        }
        __syncthreads();

        // P+ = Pn - K*T2  (= Pn - K S K^T), A = F - K*(H F)
        float krow[8];
        #pragma unroll
        for (int k = 0; k < 8; k++) krow[k] = sK[i*9+k];
        float pp = sPn[ij9];
        float aa = sF[ij9];
        #pragma unroll
        for (int k = 0; k < 8; k++) {
            pp = fmaf(-krow[k], sST2[80 + k*9+j], pp);
            aa = fmaf(-krow[k], sHF[k*9+j], aa);
        }
        sTmp[ij9] = pp;
        __syncthreads();
        float pnew = 0.5f * (pp + sTmp[j*9+i]);   // symmetrize
        float pold = sP[ij9];
        sP[ij9] = pnew;

        // outputs
        Ps_out[(size_t)t*64 + tid]       = pnew;
        g_AK[(size_t)t*144 + ij9]        = aa;
        g_AK[(size_t)t*144 + 72 + ij9]   = krow[j];   // K[i][j]

        // convergence reduction (max |dP|, max |P|)
        float dm = fabsf(pnew - pold);
        float pm = fabsf(pnew);
        #pragma unroll
        for (int o = 16; o > 0; o >>= 1) {
            dm = fmaxf(dm, __shfl_xor_sync(0xFFFFFFFFu, dm, o));
            pm = fmaxf(pm, __shfl_xor_sync(0xFFFFFFFFu, pm, o));
        }
        if ((tid & 31) == 0) { sRed[(tid>>5)*2] = dm; sRed[(tid>>5)*2+1] = pm; }
        __syncthreads();
        if (tid == 0) {
            float d = fmaxf(sRed[0], sRed[2]);
            float p = fmaxf(sRed[1], sRed[3]);
            if (t >= 32 && d < 8e-6f * p) conv++; else conv = 0;
            sFlag = (conv >= 6) ? 1 : 0;
        }
        __syncthreads();
        if (sFlag) {
            // frozen: replicate converged A, K, P for the remaining steps
            for (int tt = t + 1; tt < T; tt++) {
                g_AK[(size_t)tt*144 + ij9]      = aa;
                g_AK[(size_t)tt*144 + 72 + ij9] = krow[j];
                Ps_out[(size_t)tt*64 + tid]     = pnew;
            }
            break;
        }
    }
}

// ============================ Phase 2 ======================================

__device__ __forceinline__ void cp16(float* smem, const float* gmem) {
    unsigned s = (unsigned)__cvta_generic_to_shared(smem);
    asm volatile("cp.async.cg.shared.global [%0], [%1], 16;\n" :: "r"(s), "l"(gmem));
}
__device__ __forceinline__ void cp_commit() { asm volatile("cp.async.commit_group;\n"); }
__device__ __forceinline__ void cp_wait0()  { asm volatile("cp.async.wait_group 0;\n"); }

#define CH 40   // steps per staged chunk (1000 % 40 == 0)

__global__ void __launch_bounds__(128) traj_kernel(
    const float* __restrict__ Y, const float* __restrict__ x0,
    float* __restrict__ traj, int B, int T)
{
    __shared__ __align__(16) float sAK[2][CH * 144];
    const int tid = threadIdx.x;
    const int li  = tid & 7;                  // state component
    int bat = blockIdx.x * 16 + (tid >> 3);   // 16 batches per block
    if (bat >= B) bat = B - 1;

    float x = x0[bat * 8 + li];
    const float* yb = Y    + (size_t)bat * T * 8 + li;
    float*       ob = traj + (size_t)bat * T * 8 + li;

    const int nch   = (T + CH - 1) / CH;
    const int tot16 = (T * 144) >> 2;         // total 16B units in g_AK used

    // prefetch chunk 0
    for (int e = tid; e < CH * 36; e += 128)
        if (e < tot16) cp16(&sAK[0][e*4], &g_AK[e*4]);
    cp_commit(); cp_wait0(); __syncthreads();

    // y register ring, depth 8
    float yr[8];
    #pragma unroll
    for (int u = 0; u < 8; u++) {
        int tt = (u < T) ? u : T - 1;
        yr[u] = yb[(size_t)tt * 8];
    }

    int t = 0;
    for (int c = 0; c < nch; c++) {
        // stage next chunk asynchronously while computing the current one
        if (c + 1 < nch) {
            float* dstb = sAK[(c + 1) & 1];
            const float* srcb = g_AK + (size_t)(c + 1) * CH * 144;
            for (int e = tid; e < CH * 36; e += 128)
                if ((c + 1) * CH * 36 + e < tot16) cp16(&dstb[e*4], &srcb[e*4]);
        }
        cp_commit();

        const float* sb = sAK[c & 1];
        #pragma unroll 1
        for (int s5 = 0; s5 < CH / 8; s5++) {
            #pragma unroll
            for (int u = 0; u < 8; u++) {
                const float* ar = sb + (s5 * 8 + u) * 144 + li * 9;  // A row li
                const float* kr = ar + 72;                            // K row li
                float yv = yr[u];
                float ka = 0.f, kb = 0.f;
                #pragma unroll
                for (int k = 0; k < 8; k++) {
                    float yk = __shfl_sync(0xFFFFFFFFu, yv, k, 8);
                    if (k < 4) ka = fmaf(kr[k], yk, ka);
                    else       kb = fmaf(kr[k], yk, kb);
                }
                float xa = 0.f, xb = 0.f;
                #pragma unroll
                for (int k = 0; k < 8; k++) {
                    float xk = __shfl_sync(0xFFFFFFFFu, x, k, 8);
                    if (k < 4) xa = fmaf(ar[k], xk, xa);
                    else       xb = fmaf(ar[k], xk, xb);
                }
                float xn = (ka + xa) + (kb + xb);
                if (t < T) ob[(size_t)t * 8] = xn;
                x = xn;
                int tn = t + 8; if (tn >= T) tn = T - 1;
                yr[u] = yb[(size_t)tn * 8];
                t++;
            }
        }
        cp_wait0(); __syncthreads();
    }
}

// ============================ Launch =======================================

extern "C" void kernel_launch(void* const* d_in, const int* in_sizes, int n_in,
                              void* d_out, int out_size)
{
    // metadata order: Y, F, G, H, Q, R, x0, P0
    const float* Y  = (const float*)d_in[0];
    const float* F  = (const float*)d_in[1];
    const float* G  = (const float*)d_in[2];
    const float* H  = (const float*)d_in[3];
    const float* Q  = (const float*)d_in[4];
    const float* R  = (const float*)d_in[5];
    const float* x0 = (const float*)d_in[6];
    const float* P0 = (const float*)d_in[7];

    const int B = in_sizes[6] / 8;                 // x0 is (B, 8)
    const int T = in_sizes[0] / (B * 8);           // Y is (B, T, 8)

    float* traj = (float*)d_out;                   // (B, T, 8)
    float* Ps   = traj + (size_t)B * T * 8;        // (T, 8, 8)

    riccati_kernel<<<1, 64>>>(F, G, H, Q, R, P0, Ps, T);
    traj_kernel<<<(B + 15) / 16, 128>>>(Y, x0, traj, B, T);
}